// round 3
// baseline (speedup 1.0000x reference)
#include <cuda_runtime.h>
#include <cstddef>

// Problem constants (match reference)
constexpr int BATCH  = 32;
constexpr int SEQ    = 2048;
constexpr int V      = 500000;   // HASH_VOCAB
constexpr int D      = 128;      // EMBED_DIM
constexpr int BASE   = 257;
constexpr int NGRAMS = 6;        // n in {3,4,5,6,7,8}

// One warp per *pair* of adjacent tokens (s, s+1).
//  - windows overlap 7/8 -> 9 uniform token loads serve both hash chains
//  - 12 independent float4 gathers in flight per warp (front-batched MLP)
//  - gathers evict-normal (__ldg) to capture ~6% duplicate-index L2 hits
//  - output write-once streaming (__stcs)
__global__ __launch_bounds__(256) void byte_embed_kernel(
    const int* __restrict__ tokens,      // (B, S) int32
    const float* __restrict__ tables,    // (6, V, D) fp32
    float* __restrict__ out)             // (B, S, D) fp32
{
    const int warp_global = (blockIdx.x * blockDim.x + threadIdx.x) >> 5;
    const int lane = threadIdx.x & 31;

    // warp -> (batch row, token pair). SEQ/2 = 1024 pairs per row.
    const int b  = warp_global >> 10;
    const int p  = warp_global & 1023;
    const int s0 = 2 * p;        // even token
    const int s1 = s0 + 1;       // odd token

    const int* trow = tokens + (size_t)b * SEQ;

    // t[j] = x[s1 - j], j = 0..8  (covers both windows; s1 >= 1 always)
    int t[9];
#pragma unroll
    for (int j = 0; j < 9; ++j) {
        t[j] = (s1 - j >= 0) ? __ldg(trow + (s1 - j)) : 0;
    }

    // Rolling hash chains. After j steps, h == hash for ngram n=j+1:
    //   h_n = (h_{n-1} * 257 + x[s-(n-1)]) % V, valid when s >= n-1 else raw byte.
    int idxA[NGRAMS];  // token s1, window t[0..7]
    int idxB[NGRAMS];  // token s0, window t[1..8]
    {
        const int x0 = t[0];
        int h = x0;
#pragma unroll
        for (int j = 1; j <= 7; ++j) {
            h = (h * BASE + t[j]) % V;           // int32-safe (< 257*V + 255)
            if (j >= 2) idxA[j - 2] = (s1 >= j) ? h : x0;
        }
    }
    {
        const int x0 = t[1];
        int h = x0;
#pragma unroll
        for (int j = 1; j <= 7; ++j) {
            h = (h * BASE + t[j + 1]) % V;
            if (j >= 2) idxB[j - 2] = (s0 >= j) ? h : x0;
        }
    }

    // 12 independent coalesced float4 gathers (512B rows). 32-bit intra-table
    // offsets (idx*32 + lane < 16M elements) keep address math single-width.
    float4 accA = make_float4(0.f, 0.f, 0.f, 0.f);
    float4 accB = make_float4(0.f, 0.f, 0.f, 0.f);
#pragma unroll
    for (int k = 0; k < NGRAMS; ++k) {
        const float4* base = reinterpret_cast<const float4*>(
            tables + (size_t)k * V * D);
        float4 va = __ldg(base + ((unsigned)idxA[k] * (D / 4) + (unsigned)lane));
        float4 vb = __ldg(base + ((unsigned)idxB[k] * (D / 4) + (unsigned)lane));
        accA.x += va.x; accA.y += va.y; accA.z += va.z; accA.w += va.w;
        accB.x += vb.x; accB.y += vb.y; accB.z += vb.z; accB.w += vb.w;
    }
    const float inv = 1.0f / 6.0f;
    accA.x *= inv; accA.y *= inv; accA.z *= inv; accA.w *= inv;
    accB.x *= inv; accB.y *= inv; accB.z *= inv; accB.w *= inv;

    float4* o4 = reinterpret_cast<float4*>(out);
    const size_t row0 = (size_t)b * SEQ + s0;
    __stcs(o4 + row0 * (D / 4) + lane, accB);
    __stcs(o4 + (row0 + 1) * (D / 4) + lane, accA);
}

extern "C" void kernel_launch(void* const* d_in, const int* in_sizes, int n_in,
                              void* d_out, int out_size)
{
    (void)in_sizes; (void)n_in; (void)out_size;
    const int*   tokens = (const int*)d_in[0];
    const float* tables = (const float*)d_in[1];
    float*       out    = (float*)d_out;

    const int threads = 256;
    const int warps_needed = BATCH * (SEQ / 2);        // 32768 warps
    const int blocks = (warps_needed * 32) / threads;  // 4096
    byte_embed_kernel<<<blocks, threads>>>(tokens, tables, out);
}